// round 1
// baseline (speedup 1.0000x reference)
#include <cuda_runtime.h>
#include <cstdint>

// ---------------------------------------------------------------------------
// Problem constants
// ---------------------------------------------------------------------------
#define N_TOK 2048
#define DIM   1024
#define DFF   4096
#define HALF  2048     // DFF/2
#define INNER 512
#define DEPTH 6
#define GDEPTH 2
#define VOCAB 32
#define WSZ   512
#define NHEAD 8
#define DHEAD 64

// ---------------------------------------------------------------------------
// Scratch (device globals — no allocation allowed)
// ---------------------------------------------------------------------------
__device__ float g_x  [N_TOK * DIM];        // residual stream
__device__ float g_xn [N_TOK * DIM];        // LN(x)
__device__ float g_qkv[N_TOK * 3 * INNER];  // qkv
__device__ float g_att[N_TOK * INNER];      // attention out
__device__ float g_h  [N_TOK * DFF];        // ff / gmlp hidden
__device__ float g_gt [N_TOK * HALF];       // gate (post-LN), reused
__device__ float g_tp [N_TOK * HALF];       // spatial-gate output

// ---------------------------------------------------------------------------
// Helpers
// ---------------------------------------------------------------------------
__device__ __forceinline__ float gelu_f(float x) {
    // jax.nn.gelu approximate=True (tanh form)
    const float c = 0.7978845608028654f;
    float t = tanhf(c * (x + 0.044715f * x * x * x));
    return 0.5f * x * (1.0f + t);
}

// ---------------------------------------------------------------------------
// Embedding gather: x[row,:] = embed[tokens[row],:]
// ---------------------------------------------------------------------------
__global__ void embed_kernel(const int* __restrict__ tok,
                             const float* __restrict__ emb,
                             float* __restrict__ x) {
    int row = blockIdx.x;
    int t = tok[row];
    const float4* src = (const float4*)(emb + (size_t)t * DIM);
    float4* dst = (float4*)(x + (size_t)row * DIM);
    for (int i = threadIdx.x; i < DIM / 4; i += blockDim.x) dst[i] = src[i];
}

// ---------------------------------------------------------------------------
// LayerNorm (scale only, eps=1e-5). One block (256 thr) per row.
// src has leading dim lds, dst has leading dim ldd, D features.
// ---------------------------------------------------------------------------
__global__ void __launch_bounds__(256) ln_kernel(const float* __restrict__ src, int lds,
                                                 const float* __restrict__ gamma,
                                                 float* __restrict__ dst, int ldd, int D) {
    int row = blockIdx.x;
    const float* x = src + (size_t)row * lds;
    float s = 0.f, s2 = 0.f;
    for (int i = threadIdx.x; i < D; i += 256) {
        float v = x[i];
        s += v; s2 += v * v;
    }
    __shared__ float sh[64];
    #pragma unroll
    for (int o = 16; o; o >>= 1) {
        s  += __shfl_xor_sync(0xFFFFFFFFu, s,  o);
        s2 += __shfl_xor_sync(0xFFFFFFFFu, s2, o);
    }
    int warp = threadIdx.x >> 5, lane = threadIdx.x & 31;
    if (lane == 0) { sh[warp] = s; sh[32 + warp] = s2; }
    __syncthreads();
    if (warp == 0) {
        s  = (lane < 8) ? sh[lane]      : 0.f;
        s2 = (lane < 8) ? sh[32 + lane] : 0.f;
        #pragma unroll
        for (int o = 4; o; o >>= 1) {
            s  += __shfl_xor_sync(0xFFFFFFFFu, s,  o);
            s2 += __shfl_xor_sync(0xFFFFFFFFu, s2, o);
        }
        if (lane == 0) {
            float mean = s / D;
            float var  = s2 / D - mean * mean;
            sh[0] = mean;
            sh[1] = rsqrtf(var + 1e-5f);
        }
    }
    __syncthreads();
    float mean = sh[0], rstd = sh[1];
    float* y = dst + (size_t)row * ldd;
    for (int i = threadIdx.x; i < D; i += 256)
        y[i] = (x[i] - mean) * rstd * gamma[i];
}

// ---------------------------------------------------------------------------
// Generic SGEMM: C = epilogue(A[M,K] @ B[K,N])
// 128x128 tile, BK=16, 256 threads, 8x8 per thread.
// Epilogue flags:
//   F_BIAS   : + bias[n]
//   F_ROWB   : + rbias[m]
//   F_GELU   : gelu(.)
//   F_MULX   : * Xm[m*ldx + n]
//   F_RES    : + resid[m*N + n]
//   F_TRIL   : A[m,k] masked to 0 where k > m   (causal spatial gate)
// ---------------------------------------------------------------------------
enum { F_BIAS = 1, F_GELU = 2, F_RES = 4, F_TRIL = 8, F_MULX = 16, F_ROWB = 32 };

template <int FLAGS>
__global__ void __launch_bounds__(256) gemm_k(
    const float* __restrict__ A, const float* __restrict__ B,
    const float* __restrict__ bias, const float* __restrict__ rbias,
    const float* __restrict__ Xm, int ldx,
    const float* __restrict__ resid,
    float* __restrict__ C, int M, int N, int K) {

    __shared__ float As[16][128];
    __shared__ float Bs[16][128];

    const int tid = threadIdx.x;
    const int tx = tid & 15, ty = tid >> 4;
    const int bm = blockIdx.y * 128, bn = blockIdx.x * 128;

    float acc[8][8];
    #pragma unroll
    for (int i = 0; i < 8; i++)
        #pragma unroll
        for (int j = 0; j < 8; j++) acc[i][j] = 0.f;

    const int a_row = tid >> 2;          // 0..63
    const int a_col = (tid & 3) << 2;    // 0,4,8,12
    const int b_row = tid >> 5;          // 0..7
    const int b_col = (tid & 31) << 2;   // 0..124

    for (int kt = 0; kt < K; kt += 16) {
        #pragma unroll
        for (int r = 0; r < 2; r++) {
            int lm = a_row + r * 64;
            int gm = bm + lm;
            float4 v = *(const float4*)(A + (size_t)gm * K + kt + a_col);
            if (FLAGS & F_TRIL) {
                int kc = kt + a_col;
                v.x = (kc + 0 <= gm) ? v.x : 0.f;
                v.y = (kc + 1 <= gm) ? v.y : 0.f;
                v.z = (kc + 2 <= gm) ? v.z : 0.f;
                v.w = (kc + 3 <= gm) ? v.w : 0.f;
            }
            As[a_col + 0][lm] = v.x;
            As[a_col + 1][lm] = v.y;
            As[a_col + 2][lm] = v.z;
            As[a_col + 3][lm] = v.w;
        }
        #pragma unroll
        for (int r = 0; r < 2; r++) {
            int gk = kt + b_row + r * 8;
            int gn = bn + b_col;
            float4 v = make_float4(0.f, 0.f, 0.f, 0.f);
            if (gn < N) v = *(const float4*)(B + (size_t)gk * N + gn);
            *(float4*)&Bs[b_row + r * 8][b_col] = v;
        }
        __syncthreads();

        #pragma unroll
        for (int kk = 0; kk < 16; kk++) {
            float4 a0 = *(const float4*)&As[kk][ty * 8];
            float4 a1 = *(const float4*)&As[kk][ty * 8 + 4];
            float4 b0 = *(const float4*)&Bs[kk][tx * 8];
            float4 b1 = *(const float4*)&Bs[kk][tx * 8 + 4];
            float a[8] = {a0.x, a0.y, a0.z, a0.w, a1.x, a1.y, a1.z, a1.w};
            float b[8] = {b0.x, b0.y, b0.z, b0.w, b1.x, b1.y, b1.z, b1.w};
            #pragma unroll
            for (int i = 0; i < 8; i++)
                #pragma unroll
                for (int j = 0; j < 8; j++)
                    acc[i][j] += a[i] * b[j];
        }
        __syncthreads();
    }

    #pragma unroll
    for (int i = 0; i < 8; i++) {
        int gm = bm + ty * 8 + i;
        #pragma unroll
        for (int j = 0; j < 8; j++) {
            int gn = bn + tx * 8 + j;
            if (gn < N) {
                float v = acc[i][j];
                if (FLAGS & F_BIAS) v += bias[gn];
                if (FLAGS & F_ROWB) v += rbias[gm];
                if (FLAGS & F_GELU) v = gelu_f(v);
                if (FLAGS & F_MULX) v *= Xm[(size_t)gm * ldx + gn];
                if (FLAGS & F_RES)  v += resid[(size_t)gm * N + gn];
                C[(size_t)gm * N + gn] = v;
            }
        }
    }
}

// ---------------------------------------------------------------------------
// Local windowed attention (flash-style, one thread per query row).
// qkv layout: [N_TOK, 3*INNER]; q at col h*64, k at 512+h*64, v at 1024+h*64.
// Window w attends keys j in [0, 2*WSZ) mapped to token (w-1)*512 + j
// (negative token => zero-padded previous window of window 0).
// Mask: j <= i + WSZ.
// ---------------------------------------------------------------------------
__global__ void __launch_bounds__(128) attn_kernel(const float* __restrict__ qkv,
                                                   float* __restrict__ out) {
    const int h  = blockIdx.z;
    const int w  = blockIdx.y;
    const int rc = blockIdx.x;
    const int i  = rc * 128 + threadIdx.x;  // query row within window
    const int t  = w * WSZ + i;             // global token

    float q[64];
    {
        const float4* qp = (const float4*)(qkv + (size_t)t * (3 * INNER) + h * DHEAD);
        #pragma unroll
        for (int d = 0; d < 16; d++) {
            float4 v = qp[d];
            q[4 * d + 0] = v.x * 0.125f;
            q[4 * d + 1] = v.y * 0.125f;
            q[4 * d + 2] = v.z * 0.125f;
            q[4 * d + 3] = v.w * 0.125f;
        }
    }
    float o[64];
    #pragma unroll
    for (int d = 0; d < 64; d++) o[d] = 0.f;
    float m = -1e30f, l = 0.f;

    __shared__ float Ks[32][64];
    __shared__ float Vs[32][64];

    const int lr = threadIdx.x >> 2;        // key row 0..31
    const int lc = (threadIdx.x & 3) * 16;  // 0,16,32,48

    const int nchunk = min(32, rc * 4 + 20);  // ceil((rc*128+127+512+1)/32)

    for (int c = 0; c < nchunk; c++) {
        int j0 = c * 32;
        int tok = (w - 1) * WSZ + j0 + lr;
        const float* kp = qkv + (size_t)tok * (3 * INNER) + INNER + h * DHEAD + lc;
        const float* vp = kp + INNER;
        #pragma unroll
        for (int e = 0; e < 4; e++) {
            float4 kv = make_float4(0.f, 0.f, 0.f, 0.f);
            float4 vv = make_float4(0.f, 0.f, 0.f, 0.f);
            if (tok >= 0) {
                kv = *(const float4*)(kp + 4 * e);
                vv = *(const float4*)(vp + 4 * e);
            }
            *(float4*)&Ks[lr][lc + 4 * e] = kv;
            *(float4*)&Vs[lr][lc + 4 * e] = vv;
        }
        __syncthreads();

        float s[32];
        float mnew = m;
        #pragma unroll
        for (int jj = 0; jj < 32; jj++) {
            float sv = -1e30f;
            if (j0 + jj <= i + WSZ) {
                sv = 0.f;
                #pragma unroll
                for (int d = 0; d < 64; d++) sv += q[d] * Ks[jj][d];
            }
            s[jj] = sv;
            mnew = fmaxf(mnew, sv);
        }
        float corr = __expf(m - mnew);
        l *= corr;
        #pragma unroll
        for (int d = 0; d < 64; d++) o[d] *= corr;
        #pragma unroll
        for (int jj = 0; jj < 32; jj++) {
            float p = __expf(s[jj] - mnew);
            l += p;
            #pragma unroll
            for (int d = 0; d < 64; d++) o[d] += p * Vs[jj][d];
        }
        m = mnew;
        __syncthreads();
    }

    float inv = 1.f / l;
    float4* op = (float4*)(out + (size_t)t * INNER + h * DHEAD);
    #pragma unroll
    for (int d = 0; d < 16; d++) {
        float4 v;
        v.x = o[4 * d + 0] * inv;
        v.y = o[4 * d + 1] * inv;
        v.z = o[4 * d + 2] * inv;
        v.w = o[4 * d + 3] * inv;
        op[d] = v;
    }
}

// ---------------------------------------------------------------------------
// Host-side dispatch
// ---------------------------------------------------------------------------
static void gemm(int flags, const float* A, const float* B, const float* bias,
                 const float* rbias, const float* Xm, int ldx, const float* resid,
                 float* C, int M, int N, int K) {
    dim3 grid((N + 127) / 128, (M + 127) / 128);
    dim3 block(256);
    switch (flags) {
        case 0:
            gemm_k<0><<<grid, block>>>(A, B, bias, rbias, Xm, ldx, resid, C, M, N, K); break;
        case F_BIAS:
            gemm_k<F_BIAS><<<grid, block>>>(A, B, bias, rbias, Xm, ldx, resid, C, M, N, K); break;
        case F_BIAS | F_RES:
            gemm_k<F_BIAS | F_RES><<<grid, block>>>(A, B, bias, rbias, Xm, ldx, resid, C, M, N, K); break;
        case F_BIAS | F_GELU:
            gemm_k<F_BIAS | F_GELU><<<grid, block>>>(A, B, bias, rbias, Xm, ldx, resid, C, M, N, K); break;
        case F_TRIL | F_ROWB | F_MULX:
            gemm_k<F_TRIL | F_ROWB | F_MULX><<<grid, block>>>(A, B, bias, rbias, Xm, ldx, resid, C, M, N, K); break;
    }
}

extern "C" void kernel_launch(void* const* d_in, const int* in_sizes, int n_in,
                              void* d_out, int out_size) {
    (void)in_sizes; (void)n_in;
    const int*   tokens   = (const int*)  d_in[0];
    const float* embed    = (const float*)d_in[1];
    const float* attn_ln  = (const float*)d_in[2];
    const float* attn_qkv = (const float*)d_in[3];
    const float* attn_ow  = (const float*)d_in[4];
    const float* attn_ob  = (const float*)d_in[5];
    const float* ff_ln    = (const float*)d_in[6];
    const float* ff_w1    = (const float*)d_in[7];
    const float* ff_b1    = (const float*)d_in[8];
    const float* ff_w2    = (const float*)d_in[9];
    const float* ff_b2    = (const float*)d_in[10];
    const float* gl_ln    = (const float*)d_in[11];
    const float* g_win    = (const float*)d_in[12];
    const float* g_bin    = (const float*)d_in[13];
    const float* g_sln    = (const float*)d_in[14];
    const float* g_sw     = (const float*)d_in[15];
    const float* g_sb     = (const float*)d_in[16];
    const float* g_sow    = (const float*)d_in[17];
    const float* g_sob    = (const float*)d_in[18];
    const float* g_pow    = (const float*)d_in[19];
    const float* g_pob    = (const float*)d_in[20];
    const float* fin_ln   = (const float*)d_in[21];
    const float* head_w   = (const float*)d_in[22];
    const float* head_b   = (const float*)d_in[23];
    float* out = (float*)d_out;
    (void)out_size;

    float *X, *XN, *QKV, *ATT, *H, *GT, *TP;
    cudaGetSymbolAddress((void**)&X,   g_x);
    cudaGetSymbolAddress((void**)&XN,  g_xn);
    cudaGetSymbolAddress((void**)&QKV, g_qkv);
    cudaGetSymbolAddress((void**)&ATT, g_att);
    cudaGetSymbolAddress((void**)&H,   g_h);
    cudaGetSymbolAddress((void**)&GT,  g_gt);
    cudaGetSymbolAddress((void**)&TP,  g_tp);

    // x = embed[tokens]
    embed_kernel<<<N_TOK, 256>>>(tokens, embed, X);

    // 6 attention + FF blocks
    for (int l = 0; l < DEPTH; l++) {
        const float* al = attn_ln  + (size_t)l * DIM;
        const float* aq = attn_qkv + (size_t)l * DIM * 3 * INNER;
        const float* aw = attn_ow  + (size_t)l * INNER * DIM;
        const float* ab = attn_ob  + (size_t)l * DIM;
        const float* fl = ff_ln    + (size_t)l * DIM;
        const float* f1 = ff_w1    + (size_t)l * DIM * DFF;
        const float* b1 = ff_b1    + (size_t)l * DFF;
        const float* f2 = ff_w2    + (size_t)l * DFF * DIM;
        const float* b2 = ff_b2    + (size_t)l * DIM;

        ln_kernel<<<N_TOK, 256>>>(X, DIM, al, XN, DIM, DIM);
        gemm(0, XN, aq, nullptr, nullptr, nullptr, 0, nullptr, QKV, N_TOK, 3 * INNER, DIM);
        attn_kernel<<<dim3(4, 4, NHEAD), 128>>>(QKV, ATT);
        gemm(F_BIAS | F_RES, ATT, aw, ab, nullptr, nullptr, 0, X, X, N_TOK, DIM, INNER);

        ln_kernel<<<N_TOK, 256>>>(X, DIM, fl, XN, DIM, DIM);
        gemm(F_BIAS | F_GELU, XN, f1, b1, nullptr, nullptr, 0, nullptr, H, N_TOK, DFF, DIM);
        gemm(F_BIAS | F_RES, H, f2, b2, nullptr, nullptr, 0, X, X, N_TOK, DIM, DFF);
    }

    // 2 gMLP blocks
    for (int g = 0; g < GDEPTH; g++) {
        const float* gl  = gl_ln + (size_t)g * DIM;
        const float* wi  = g_win + (size_t)g * DIM * DFF;
        const float* bi  = g_bin + (size_t)g * DFF;
        const float* sl  = g_sln + (size_t)g * HALF;
        const float* sw  = g_sw  + (size_t)g * N_TOK * N_TOK;
        const float* sb  = g_sb  + (size_t)g * N_TOK;
        const float* so  = g_sow + (size_t)g * HALF * HALF;
        const float* sob = g_sob + (size_t)g * HALF;
        const float* po  = g_pow + (size_t)g * HALF * DIM;
        const float* pob = g_pob + (size_t)g * DIM;

        ln_kernel<<<N_TOK, 256>>>(X, DIM, gl, XN, DIM, DIM);
        gemm(F_BIAS | F_GELU, XN, wi, bi, nullptr, nullptr, 0, nullptr, H, N_TOK, DFF, DIM);
        // gate = LN(h[:, 2048:4096])
        ln_kernel<<<N_TOK, 256>>>(H + HALF, DFF, sl, GT, HALF, HALF);
        // TP = xg * (tril(sw) @ gate + sb)   (xg = h[:, :2048], row stride DFF)
        gemm(F_TRIL | F_ROWB | F_MULX, sw, GT, nullptr, sb, H, DFF, nullptr, TP,
             N_TOK, HALF, N_TOK);
        // GT = TP @ sow + sob
        gemm(F_BIAS, TP, so, sob, nullptr, nullptr, 0, nullptr, GT, N_TOK, HALF, HALF);
        // x += GT @ pow + pob
        gemm(F_BIAS | F_RES, GT, po, pob, nullptr, nullptr, 0, X, X, N_TOK, DIM, HALF);
    }

    // head
    ln_kernel<<<N_TOK, 256>>>(X, DIM, fin_ln, XN, DIM, DIM);
    gemm(F_BIAS, XN, head_w, head_b, nullptr, nullptr, 0, nullptr, out, N_TOK, VOCAB, DIM);
}

// round 2
// speedup vs baseline: 1.9737x; 1.9737x over previous
#include <cuda_runtime.h>
#include <cstdint>

// ---------------------------------------------------------------------------
// Problem constants
// ---------------------------------------------------------------------------
#define N_TOK 2048
#define DIM   1024
#define DFF   4096
#define HALF  2048     // DFF/2
#define INNER 512
#define DEPTH 6
#define GDEPTH 2
#define VOCAB 32
#define WSZ   512
#define NHEAD 8
#define DHEAD 64

// ---------------------------------------------------------------------------
// Scratch (device globals — no allocation allowed)
// ---------------------------------------------------------------------------
__device__ float g_x  [N_TOK * DIM];
__device__ float g_xn [N_TOK * DIM];
__device__ float g_qkv[N_TOK * 3 * INNER];
__device__ float g_att[N_TOK * INNER];
__device__ float g_h  [N_TOK * DFF];
__device__ float g_gt [N_TOK * HALF];
__device__ float g_tp [N_TOK * HALF];

// ---------------------------------------------------------------------------
// Helpers
// ---------------------------------------------------------------------------
__device__ __forceinline__ float gelu_f(float x) {
    const float c = 0.7978845608028654f;
    float t = tanhf(c * (x + 0.044715f * x * x * x));
    return 0.5f * x * (1.0f + t);
}

__device__ __forceinline__ uint32_t to_tf32(float v) {
    uint32_t r;
    asm("cvt.rna.tf32.f32 %0, %1;" : "=r"(r) : "f"(v));
    return r;
}

__device__ __forceinline__ void mma8(float* c, const uint32_t* a, const uint32_t* b) {
    asm volatile(
        "mma.sync.aligned.m16n8k8.row.col.f32.tf32.tf32.f32 "
        "{%0,%1,%2,%3}, {%4,%5,%6,%7}, {%8,%9}, {%0,%1,%2,%3};"
        : "+f"(c[0]), "+f"(c[1]), "+f"(c[2]), "+f"(c[3])
        : "r"(a[0]), "r"(a[1]), "r"(a[2]), "r"(a[3]), "r"(b[0]), "r"(b[1]));
}

// ---------------------------------------------------------------------------
// Embedding gather
// ---------------------------------------------------------------------------
__global__ void embed_kernel(const int* __restrict__ tok,
                             const float* __restrict__ emb,
                             float* __restrict__ x) {
    int row = blockIdx.x;
    int t = tok[row];
    const float4* src = (const float4*)(emb + (size_t)t * DIM);
    float4* dst = (float4*)(x + (size_t)row * DIM);
    for (int i = threadIdx.x; i < DIM / 4; i += blockDim.x) dst[i] = src[i];
}

// ---------------------------------------------------------------------------
// LayerNorm (scale only, eps=1e-5). One block (256 thr) per row.
// ---------------------------------------------------------------------------
__global__ void __launch_bounds__(256) ln_kernel(const float* __restrict__ src, int lds,
                                                 const float* __restrict__ gamma,
                                                 float* __restrict__ dst, int ldd, int D) {
    int row = blockIdx.x;
    const float* x = src + (size_t)row * lds;
    float s = 0.f, s2 = 0.f;
    for (int i = threadIdx.x; i < D; i += 256) {
        float v = x[i];
        s += v; s2 += v * v;
    }
    __shared__ float sh[64];
    #pragma unroll
    for (int o = 16; o; o >>= 1) {
        s  += __shfl_xor_sync(0xFFFFFFFFu, s,  o);
        s2 += __shfl_xor_sync(0xFFFFFFFFu, s2, o);
    }
    int warp = threadIdx.x >> 5, lane = threadIdx.x & 31;
    if (lane == 0) { sh[warp] = s; sh[32 + warp] = s2; }
    __syncthreads();
    if (warp == 0) {
        s  = (lane < 8) ? sh[lane]      : 0.f;
        s2 = (lane < 8) ? sh[32 + lane] : 0.f;
        #pragma unroll
        for (int o = 4; o; o >>= 1) {
            s  += __shfl_xor_sync(0xFFFFFFFFu, s,  o);
            s2 += __shfl_xor_sync(0xFFFFFFFFu, s2, o);
        }
        if (lane == 0) {
            float mean = s / D;
            float var  = s2 / D - mean * mean;
            sh[0] = mean;
            sh[1] = rsqrtf(var + 1e-5f);
        }
    }
    __syncthreads();
    float mean = sh[0], rstd = sh[1];
    float* y = dst + (size_t)row * ldd;
    for (int i = threadIdx.x; i < D; i += 256)
        y[i] = (x[i] - mean) * rstd * gamma[i];
}

// ---------------------------------------------------------------------------
// tf32 tensor-core GEMM: C = epilogue(A[M,K] @ B[K,N])
// 128x128 CTA tile, BK=32, 256 threads / 8 warps, warp tile 32x64.
// SMEM holds mma fragments directly (lane-linear ld.shared.v2 reads) with an
// XOR swizzle for bank-conflict-free access.
//
// A fragment slot (per k8 group g, m16 tile t, pair p):  64 words,
//   word = ((g*8+t)*2+p)*64 + ((slotlane*2 + pos) ^ (2*((m>>2)&3)))
//   slotlane = ((m&7)<<2)|(k&3), pos = (k>>2)&1
// B fragment slot (per g, n8 tile u): 64 words,
//   word = (g*16+u)*64 + ((slotlane*2 + pos) ^ (2*u))
//   slotlane = ((n&7)<<2)|(k&3), pos = (k>>2)&1
// ---------------------------------------------------------------------------
enum { F_BIAS = 1, F_GELU = 2, F_RES = 4, F_TRIL = 8, F_MULX = 16, F_ROWB = 32 };

template <int FLAGS>
__global__ void __launch_bounds__(256) gemm_tc(
    const float* __restrict__ A, const float* __restrict__ B,
    const float* __restrict__ bias, const float* __restrict__ rbias,
    const float* __restrict__ Xm, int ldx,
    const float* __restrict__ resid,
    float* __restrict__ C, int M, int N, int K) {

    __shared__ uint32_t As[4096];   // 16 KB
    __shared__ uint32_t Bs[4096];   // 16 KB

    const int tid  = threadIdx.x;
    const int lane = tid & 31;
    const int wid  = tid >> 5;
    const int wm   = wid >> 1;      // 0..3 -> rows wm*32
    const int wn   = wid & 1;       // 0..1 -> cols wn*64
    const int bm = blockIdx.y * 128, bn = blockIdx.x * 128;

    float acc[2][8][4];
    #pragma unroll
    for (int i = 0; i < 2; i++)
        #pragma unroll
        for (int j = 0; j < 8; j++)
            #pragma unroll
            for (int e = 0; e < 4; e++) acc[i][j][e] = 0.f;

    // ---- loader thread mapping ----
    const int am  = tid >> 1;           // A row 0..127
    const int akh = (tid & 1) * 16;     // A k half
    const int bk  = tid >> 3;           // B k 0..31
    const int bn0 = (tid & 7) * 16;     // B n base

    const int a_t    = am >> 4;
    const int a_pair = (am >> 3) & 1;
    const int a_sl   = (am & 7) << 2;
    const int a_x    = 2 * ((am >> 2) & 3);
    const int b_g    = bk >> 3;
    const int b_pos  = (bk >> 2) & 1;
    const int b_kl   = bk & 3;

    // ---- fragment read offsets ----
    const int axoff0 = (lane * 2) ^ (2 * (lane >> 4));
    const int axoff1 = (lane * 2) ^ (2 * (lane >> 4) + 4);
    int boff[8];
    #pragma unroll
    for (int nt = 0; nt < 8; nt++) {
        int u = wn * 8 + nt;
        boff[nt] = u * 64 + ((lane * 2) ^ (2 * u));
    }

    float4 pa[4], pb[4];

    // ---- initial GMEM prefetch (kt = 0) ----
    {
        const float* ap = A + (size_t)(bm + am) * K + akh;
        #pragma unroll
        for (int f = 0; f < 4; f++) pa[f] = *(const float4*)(ap + f * 4);
        if (FLAGS & F_TRIL) {
            int gm = bm + am;
            #pragma unroll
            for (int f = 0; f < 4; f++) {
                int kb = akh + f * 4;
                if (kb + 0 > gm) pa[f].x = 0.f;
                if (kb + 1 > gm) pa[f].y = 0.f;
                if (kb + 2 > gm) pa[f].z = 0.f;
                if (kb + 3 > gm) pa[f].w = 0.f;
            }
        }
        #pragma unroll
        for (int f = 0; f < 4; f++) {
            int gn = bn + bn0 + f * 4;
            pb[f] = (gn < N) ? *(const float4*)(B + (size_t)bk * N + gn)
                             : make_float4(0.f, 0.f, 0.f, 0.f);
        }
    }

    for (int kt = 0; kt < K; kt += 32) {
        __syncthreads();   // previous tile fully consumed

        // ---- store staged registers -> fragment SMEM (with tf32 round) ----
        #pragma unroll
        for (int f = 0; f < 4; f++) {
            float vv[4] = {pa[f].x, pa[f].y, pa[f].z, pa[f].w};
            #pragma unroll
            for (int e = 0; e < 4; e++) {
                int k = akh + f * 4 + e;
                int g = k >> 3, pos = (k >> 2) & 1, kl = k & 3;
                int word = ((g * 8 + a_t) * 2 + a_pair) * 64 +
                           (((a_sl | kl) * 2 + pos) ^ a_x);
                As[word] = to_tf32(vv[e]);
            }
        }
        #pragma unroll
        for (int f = 0; f < 4; f++) {
            float vv[4] = {pb[f].x, pb[f].y, pb[f].z, pb[f].w};
            #pragma unroll
            for (int e = 0; e < 4; e++) {
                int n = bn0 + f * 4 + e;
                int u = n >> 3;
                int word = (b_g * 16 + u) * 64 +
                           (((((n & 7) << 2) | b_kl) * 2 + b_pos) ^ (2 * u));
                Bs[word] = to_tf32(vv[e]);
            }
        }
        __syncthreads();

        // ---- prefetch next tile while computing ----
        if (kt + 32 < K) {
            const float* ap = A + (size_t)(bm + am) * K + kt + 32 + akh;
            #pragma unroll
            for (int f = 0; f < 4; f++) pa[f] = *(const float4*)(ap + f * 4);
            if (FLAGS & F_TRIL) {
                int gm = bm + am;
                #pragma unroll
                for (int f = 0; f < 4; f++) {
                    int kb = kt + 32 + akh + f * 4;
                    if (kb + 0 > gm) pa[f].x = 0.f;
                    if (kb + 1 > gm) pa[f].y = 0.f;
                    if (kb + 2 > gm) pa[f].z = 0.f;
                    if (kb + 3 > gm) pa[f].w = 0.f;
                }
            }
            #pragma unroll
            for (int f = 0; f < 4; f++) {
                int gn = bn + bn0 + f * 4;
                pb[f] = (gn < N) ? *(const float4*)(B + (size_t)(kt + 32 + bk) * N + gn)
                                 : make_float4(0.f, 0.f, 0.f, 0.f);
            }
        }

        // ---- compute: 4 k8-steps x (2 m-tiles x 8 n-tiles) mma ----
        #pragma unroll
        for (int g = 0; g < 4; g++) {
            uint32_t af[2][4];
            #pragma unroll
            for (int mt = 0; mt < 2; mt++) {
                int seg0 = ((g * 8 + wm * 2 + mt) * 2) * 64;
                uint2 v0 = *(const uint2*)&As[seg0 + axoff0];
                uint2 v1 = *(const uint2*)&As[seg0 + 64 + axoff1];
                af[mt][0] = v0.x; af[mt][2] = v0.y;
                af[mt][1] = v1.x; af[mt][3] = v1.y;
            }
            uint32_t bf[8][2];
            #pragma unroll
            for (int nt = 0; nt < 8; nt++) {
                uint2 v = *(const uint2*)&Bs[g * 1024 + boff[nt]];
                bf[nt][0] = v.x; bf[nt][1] = v.y;
            }
            #pragma unroll
            for (int mt = 0; mt < 2; mt++)
                #pragma unroll
                for (int nt = 0; nt < 8; nt++)
                    mma8(acc[mt][nt], af[mt], bf[nt]);
        }
    }

    // ---- epilogue ----
    const int r0 = bm + wm * 32 + (lane >> 2);
    const int cb = bn + wn * 64 + (lane & 3) * 2;
    #pragma unroll
    for (int mt = 0; mt < 2; mt++) {
        #pragma unroll
        for (int nt = 0; nt < 8; nt++) {
            float* a4 = acc[mt][nt];
            int gm = r0 + mt * 16;
            int gn = cb + nt * 8;
            #pragma unroll
            for (int e = 0; e < 4; e++) {
                int rr = gm + (e >> 1) * 8;
                int cc = gn + (e & 1);
                if (cc < N) {
                    float v = a4[e];
                    if (FLAGS & F_BIAS) v += bias[cc];
                    if (FLAGS & F_ROWB) v += rbias[rr];
                    if (FLAGS & F_GELU) v = gelu_f(v);
                    if (FLAGS & F_MULX) v *= Xm[(size_t)rr * ldx + cc];
                    if (FLAGS & F_RES)  v += resid[(size_t)rr * N + cc];
                    C[(size_t)rr * N + cc] = v;
                }
            }
        }
    }
}

// ---------------------------------------------------------------------------
// Local windowed attention (flash-style, one thread per query row).
// ---------------------------------------------------------------------------
__global__ void __launch_bounds__(128) attn_kernel(const float* __restrict__ qkv,
                                                   float* __restrict__ out) {
    const int h  = blockIdx.z;
    const int w  = blockIdx.y;
    const int rc = blockIdx.x;
    const int i  = rc * 128 + threadIdx.x;
    const int t  = w * WSZ + i;

    float q[64];
    {
        const float4* qp = (const float4*)(qkv + (size_t)t * (3 * INNER) + h * DHEAD);
        #pragma unroll
        for (int d = 0; d < 16; d++) {
            float4 v = qp[d];
            q[4 * d + 0] = v.x * 0.125f;
            q[4 * d + 1] = v.y * 0.125f;
            q[4 * d + 2] = v.z * 0.125f;
            q[4 * d + 3] = v.w * 0.125f;
        }
    }
    float o[64];
    #pragma unroll
    for (int d = 0; d < 64; d++) o[d] = 0.f;
    float m = -1e30f, l = 0.f;

    __shared__ float Ks[32][64];
    __shared__ float Vs[32][64];

    const int lr = threadIdx.x >> 2;
    const int lc = (threadIdx.x & 3) * 16;
    const int nchunk = min(32, rc * 4 + 20);

    for (int c = 0; c < nchunk; c++) {
        int j0 = c * 32;
        int tok = (w - 1) * WSZ + j0 + lr;
        const float* kp = qkv + (size_t)tok * (3 * INNER) + INNER + h * DHEAD + lc;
        const float* vp = kp + INNER;
        #pragma unroll
        for (int e = 0; e < 4; e++) {
            float4 kv = make_float4(0.f, 0.f, 0.f, 0.f);
            float4 vv = make_float4(0.f, 0.f, 0.f, 0.f);
            if (tok >= 0) {
                kv = *(const float4*)(kp + 4 * e);
                vv = *(const float4*)(vp + 4 * e);
            }
            *(float4*)&Ks[lr][lc + 4 * e] = kv;
            *(float4*)&Vs[lr][lc + 4 * e] = vv;
        }
        __syncthreads();

        float s[32];
        float mnew = m;
        #pragma unroll
        for (int jj = 0; jj < 32; jj++) {
            float sv = -1e30f;
            if (j0 + jj <= i + WSZ) {
                sv = 0.f;
                #pragma unroll
                for (int d = 0; d < 64; d++) sv += q[d] * Ks[jj][d];
            }
            s[jj] = sv;
            mnew = fmaxf(mnew, sv);
        }
        float corr = __expf(m - mnew);
        l *= corr;
        #pragma unroll
        for (int d = 0; d < 64; d++) o[d] *= corr;
        #pragma unroll
        for (int jj = 0; jj < 32; jj++) {
            float p = __expf(s[jj] - mnew);
            l += p;
            #pragma unroll
            for (int d = 0; d < 64; d++) o[d] += p * Vs[jj][d];
        }
        m = mnew;
        __syncthreads();
    }

    float inv = 1.f / l;
    float4* op = (float4*)(out + (size_t)t * INNER + h * DHEAD);
    #pragma unroll
    for (int d = 0; d < 16; d++) {
        float4 v;
        v.x = o[4 * d + 0] * inv;
        v.y = o[4 * d + 1] * inv;
        v.z = o[4 * d + 2] * inv;
        v.w = o[4 * d + 3] * inv;
        op[d] = v;
    }
}

// ---------------------------------------------------------------------------
// Host-side dispatch
// ---------------------------------------------------------------------------
static void gemm(int flags, const float* A, const float* B, const float* bias,
                 const float* rbias, const float* Xm, int ldx, const float* resid,
                 float* C, int M, int N, int K) {
    dim3 grid((N + 127) / 128, (M + 127) / 128);
    dim3 block(256);
    switch (flags) {
        case 0:
            gemm_tc<0><<<grid, block>>>(A, B, bias, rbias, Xm, ldx, resid, C, M, N, K); break;
        case F_BIAS:
            gemm_tc<F_BIAS><<<grid, block>>>(A, B, bias, rbias, Xm, ldx, resid, C, M, N, K); break;
        case F_BIAS | F_RES:
            gemm_tc<F_BIAS | F_RES><<<grid, block>>>(A, B, bias, rbias, Xm, ldx, resid, C, M, N, K); break;
        case F_BIAS | F_GELU:
            gemm_tc<F_BIAS | F_GELU><<<grid, block>>>(A, B, bias, rbias, Xm, ldx, resid, C, M, N, K); break;
        case F_TRIL | F_ROWB | F_MULX:
            gemm_tc<F_TRIL | F_ROWB | F_MULX><<<grid, block>>>(A, B, bias, rbias, Xm, ldx, resid, C, M, N, K); break;
    }
}

extern "C" void kernel_launch(void* const* d_in, const int* in_sizes, int n_in,
                              void* d_out, int out_size) {
    (void)in_sizes; (void)n_in;
    const int*   tokens   = (const int*)  d_in[0];
    const float* embed    = (const float*)d_in[1];
    const float* attn_ln  = (const float*)d_in[2];
    const float* attn_qkv = (const float*)d_in[3];
    const float* attn_ow  = (const float*)d_in[4];
    const float* attn_ob  = (const float*)d_in[5];
    const float* ff_ln    = (const float*)d_in[6];
    const float* ff_w1    = (const float*)d_in[7];
    const float* ff_b1    = (const float*)d_in[8];
    const float* ff_w2    = (const float*)d_in[9];
    const float* ff_b2    = (const float*)d_in[10];
    const float* gl_ln    = (const float*)d_in[11];
    const float* g_win    = (const float*)d_in[12];
    const float* g_bin    = (const float*)d_in[13];
    const float* g_sln    = (const float*)d_in[14];
    const float* g_sw     = (const float*)d_in[15];
    const float* g_sb     = (const float*)d_in[16];
    const float* g_sow    = (const float*)d_in[17];
    const float* g_sob    = (const float*)d_in[18];
    const float* g_pow    = (const float*)d_in[19];
    const float* g_pob    = (const float*)d_in[20];
    const float* fin_ln   = (const float*)d_in[21];
    const float* head_w   = (const float*)d_in[22];
    const float* head_b   = (const float*)d_in[23];
    float* out = (float*)d_out;
    (void)out_size;

    float *X, *XN, *QKV, *ATT, *H, *GT, *TP;
    cudaGetSymbolAddress((void**)&X,   g_x);
    cudaGetSymbolAddress((void**)&XN,  g_xn);
    cudaGetSymbolAddress((void**)&QKV, g_qkv);
    cudaGetSymbolAddress((void**)&ATT, g_att);
    cudaGetSymbolAddress((void**)&H,   g_h);
    cudaGetSymbolAddress((void**)&GT,  g_gt);
    cudaGetSymbolAddress((void**)&TP,  g_tp);

    embed_kernel<<<N_TOK, 256>>>(tokens, embed, X);

    for (int l = 0; l < DEPTH; l++) {
        const float* al = attn_ln  + (size_t)l * DIM;
        const float* aq = attn_qkv + (size_t)l * DIM * 3 * INNER;
        const float* aw = attn_ow  + (size_t)l * INNER * DIM;
        const float* ab = attn_ob  + (size_t)l * DIM;
        const float* fl = ff_ln    + (size_t)l * DIM;
        const float* f1 = ff_w1    + (size_t)l * DIM * DFF;
        const float* b1 = ff_b1    + (size_t)l * DFF;
        const float* f2 = ff_w2    + (size_t)l * DFF * DIM;
        const float* b2 = ff_b2    + (size_t)l * DIM;

        ln_kernel<<<N_TOK, 256>>>(X, DIM, al, XN, DIM, DIM);
        gemm(0, XN, aq, nullptr, nullptr, nullptr, 0, nullptr, QKV, N_TOK, 3 * INNER, DIM);
        attn_kernel<<<dim3(4, 4, NHEAD), 128>>>(QKV, ATT);
        gemm(F_BIAS | F_RES, ATT, aw, ab, nullptr, nullptr, 0, X, X, N_TOK, DIM, INNER);

        ln_kernel<<<N_TOK, 256>>>(X, DIM, fl, XN, DIM, DIM);
        gemm(F_BIAS | F_GELU, XN, f1, b1, nullptr, nullptr, 0, nullptr, H, N_TOK, DFF, DIM);
        gemm(F_BIAS | F_RES, H, f2, b2, nullptr, nullptr, 0, X, X, N_TOK, DIM, DFF);
    }

    for (int g = 0; g < GDEPTH; g++) {
        const float* gl  = gl_ln + (size_t)g * DIM;
        const float* wi  = g_win + (size_t)g * DIM * DFF;
        const float* bi  = g_bin + (size_t)g * DFF;
        const float* sl  = g_sln + (size_t)g * HALF;
        const float* sw  = g_sw  + (size_t)g * N_TOK * N_TOK;
        const float* sb  = g_sb  + (size_t)g * N_TOK;
        const float* so  = g_sow + (size_t)g * HALF * HALF;
        const float* sob = g_sob + (size_t)g * HALF;
        const float* po  = g_pow + (size_t)g * HALF * DIM;
        const float* pob = g_pob + (size_t)g * DIM;

        ln_kernel<<<N_TOK, 256>>>(X, DIM, gl, XN, DIM, DIM);
        gemm(F_BIAS | F_GELU, XN, wi, bi, nullptr, nullptr, 0, nullptr, H, N_TOK, DFF, DIM);
        ln_kernel<<<N_TOK, 256>>>(H + HALF, DFF, sl, GT, HALF, HALF);
        gemm(F_TRIL | F_ROWB | F_MULX, sw, GT, nullptr, sb, H, DFF, nullptr, TP,
             N_TOK, HALF, N_TOK);
        gemm(F_BIAS, TP, so, sob, nullptr, nullptr, 0, nullptr, GT, N_TOK, HALF, HALF);
        gemm(F_BIAS | F_RES, GT, po, pob, nullptr, nullptr, 0, X, X, N_TOK, DIM, HALF);
    }

    ln_kernel<<<N_TOK, 256>>>(X, DIM, fin_ln, XN, DIM, DIM);
    gemm(F_BIAS, XN, head_w, head_b, nullptr, nullptr, 0, nullptr, out, N_TOK, VOCAB, DIM);
}

// round 4
// speedup vs baseline: 2.0479x; 1.0376x over previous
#include <cuda_runtime.h>
#include <cuda_bf16.h>
#include <cstdint>

// ---------------------------------------------------------------------------
// Problem constants
// ---------------------------------------------------------------------------
#define N_TOK 2048
#define DIM   1024
#define DFF   4096
#define HALF  2048
#define INNER 512
#define DEPTH 6
#define GDEPTH 2
#define VOCAB 32
#define WSZ   512
#define NHEAD 8
#define DHEAD 64

// ---------------------------------------------------------------------------
// Scratch (device globals — no allocation allowed)
// ---------------------------------------------------------------------------
__device__ float g_x  [N_TOK * DIM];
__device__ float g_xn [N_TOK * DIM];
__device__ float g_qkv[N_TOK * 3 * INNER];
__device__ float g_att[N_TOK * INNER];
__device__ float g_h  [N_TOK * DFF];
__device__ float g_gt [N_TOK * HALF];
__device__ float g_tp [N_TOK * HALF];
// bf16 split buffers
__device__ __nv_bfloat16 g_ahi[N_TOK * DFF];      // A hi  [M][K], max 8M elems
__device__ __nv_bfloat16 g_alo[N_TOK * DFF];      // A lo
__device__ __nv_bfloat16 g_bhi[4 * 1024 * 1024];  // Bt hi [N][K], max 4M elems
__device__ __nv_bfloat16 g_blo[4 * 1024 * 1024];  // Bt lo

// ---------------------------------------------------------------------------
// Helpers
// ---------------------------------------------------------------------------
__device__ __forceinline__ float gelu_f(float x) {
    const float c = 0.7978845608028654f;
    float t = tanhf(c * (x + 0.044715f * x * x * x));
    return 0.5f * x * (1.0f + t);
}

__device__ __forceinline__ uint32_t s2u(const void* p) {
    uint32_t a;
    asm("{ .reg .u64 t; cvta.to.shared.u64 t, %1; cvt.u32.u64 %0, t; }"
        : "=r"(a) : "l"(p));
    return a;
}

#define CP_ASYNC16(dst, src) \
    asm volatile("cp.async.cg.shared.global [%0], [%1], 16;" :: "r"(dst), "l"(src))
#define CP_COMMIT() asm volatile("cp.async.commit_group;" ::: "memory")
#define CP_WAIT1()  asm volatile("cp.async.wait_group 1;" ::: "memory")
#define CP_WAIT0()  asm volatile("cp.async.wait_group 0;" ::: "memory")

#define LDSM4(r, addr) \
    asm volatile("ldmatrix.sync.aligned.m8n8.x4.shared.b16 {%0,%1,%2,%3}, [%4];" \
                 : "=r"((r)[0]), "=r"((r)[1]), "=r"((r)[2]), "=r"((r)[3]) : "r"(addr))

__device__ __forceinline__ void mma_bf16(float* c, const uint32_t* a, const uint32_t* b) {
    asm volatile(
        "mma.sync.aligned.m16n8k16.row.col.f32.bf16.bf16.f32 "
        "{%0,%1,%2,%3}, {%4,%5,%6,%7}, {%8,%9}, {%0,%1,%2,%3};"
        : "+f"(c[0]), "+f"(c[1]), "+f"(c[2]), "+f"(c[3])
        : "r"(a[0]), "r"(a[1]), "r"(a[2]), "r"(a[3]), "r"(b[0]), "r"(b[1]));
}

__device__ __forceinline__ uint32_t pack_bf2(float a, float b) {
    __nv_bfloat162 h = __floats2bfloat162_rn(a, b);
    return *(uint32_t*)&h;
}

// ---------------------------------------------------------------------------
// Embedding gather
// ---------------------------------------------------------------------------
__global__ void embed_kernel(const int* __restrict__ tok,
                             const float* __restrict__ emb,
                             float* __restrict__ x) {
    int row = blockIdx.x;
    int t = tok[row];
    const float4* src = (const float4*)(emb + (size_t)t * DIM);
    float4* dst = (float4*)(x + (size_t)row * DIM);
    for (int i = threadIdx.x; i < DIM / 4; i += blockDim.x) dst[i] = src[i];
}

// ---------------------------------------------------------------------------
// LayerNorm
// ---------------------------------------------------------------------------
__global__ void __launch_bounds__(256) ln_kernel(const float* __restrict__ src, int lds,
                                                 const float* __restrict__ gamma,
                                                 float* __restrict__ dst, int ldd, int D) {
    int row = blockIdx.x;
    const float* x = src + (size_t)row * lds;
    float s = 0.f, s2 = 0.f;
    for (int i = threadIdx.x; i < D; i += 256) {
        float v = x[i];
        s += v; s2 += v * v;
    }
    __shared__ float sh[64];
    #pragma unroll
    for (int o = 16; o; o >>= 1) {
        s  += __shfl_xor_sync(0xFFFFFFFFu, s,  o);
        s2 += __shfl_xor_sync(0xFFFFFFFFu, s2, o);
    }
    int warp = threadIdx.x >> 5, lane = threadIdx.x & 31;
    if (lane == 0) { sh[warp] = s; sh[32 + warp] = s2; }
    __syncthreads();
    if (warp == 0) {
        s  = (lane < 8) ? sh[lane]      : 0.f;
        s2 = (lane < 8) ? sh[32 + lane] : 0.f;
        #pragma unroll
        for (int o = 4; o; o >>= 1) {
            s  += __shfl_xor_sync(0xFFFFFFFFu, s,  o);
            s2 += __shfl_xor_sync(0xFFFFFFFFu, s2, o);
        }
        if (lane == 0) {
            float mean = s / D;
            float var  = s2 / D - mean * mean;
            sh[0] = mean;
            sh[1] = rsqrtf(var + 1e-5f);
        }
    }
    __syncthreads();
    float mean = sh[0], rstd = sh[1];
    float* y = dst + (size_t)row * ldd;
    for (int i = threadIdx.x; i < D; i += 256)
        y[i] = (x[i] - mean) * rstd * gamma[i];
}

// ---------------------------------------------------------------------------
// Split A (fp32 -> bf16 hi/lo), optional tril mask (k>m -> 0). 4 elems/thread.
// ---------------------------------------------------------------------------
__global__ void __launch_bounds__(256) splitA_k(const float* __restrict__ A,
                                                __nv_bfloat16* __restrict__ hi,
                                                __nv_bfloat16* __restrict__ lo,
                                                int MK, int K, int tril) {
    int i4 = (blockIdx.x * 256 + threadIdx.x) * 4;
    if (i4 >= MK) return;
    float4 v = *(const float4*)(A + i4);
    float vv[4] = {v.x, v.y, v.z, v.w};
    if (tril) {
        int m = i4 / K, k = i4 - m * K;   // 4 elems same row (K mult of 4)
        #pragma unroll
        for (int e = 0; e < 4; e++)
            if (k + e > m) vv[e] = 0.f;
    }
    float hf[4], lf[4];
    #pragma unroll
    for (int e = 0; e < 4; e++) {
        hf[e] = __bfloat162float(__float2bfloat16(vv[e]));
        lf[e] = vv[e] - hf[e];
    }
    uint2 ho, lo2;
    ho.x  = pack_bf2(hf[0], hf[1]); ho.y  = pack_bf2(hf[2], hf[3]);
    lo2.x = pack_bf2(lf[0], lf[1]); lo2.y = pack_bf2(lf[2], lf[3]);
    *(uint2*)(hi + i4) = ho;
    *(uint2*)(lo + i4) = lo2;
}

// ---------------------------------------------------------------------------
// Transpose + split B: B[K][N] fp32 -> Bt hi/lo bf16 [N][K]
// ---------------------------------------------------------------------------
__global__ void __launch_bounds__(256) tspB_k(const float* __restrict__ B,
                                              __nv_bfloat16* __restrict__ hi,
                                              __nv_bfloat16* __restrict__ lo,
                                              int K, int N) {
    __shared__ float sh[32][33];
    int nt = blockIdx.x * 32, kt = blockIdx.y * 32;
    int tx = threadIdx.x & 31, ty = threadIdx.x >> 5;
    #pragma unroll
    for (int j = 0; j < 32; j += 8)
        sh[ty + j][tx] = B[(size_t)(kt + ty + j) * N + nt + tx];
    __syncthreads();
    #pragma unroll
    for (int j = 0; j < 32; j += 8) {
        float v = sh[tx][ty + j];
        float h = __bfloat162float(__float2bfloat16(v));
        size_t o = (size_t)(nt + ty + j) * K + kt + tx;
        hi[o] = __float2bfloat16(h);
        lo[o] = __float2bfloat16(v - h);
    }
}

// ---------------------------------------------------------------------------
// Split-bf16 3-term tensor-core GEMM: C = epilogue(A @ B)
// A = Ahi+Alo [M][K] bf16, Bt = Bhi+Blo [N][K] bf16.
// 128x128 CTA tile, BK=32, 256 thr / 8 warps, warp tile 32x64.
// cp.async double-buffer; SMEM rows padded to 80B (conflict-free ldmatrix).
// ---------------------------------------------------------------------------
enum { F_BIAS = 1, F_GELU = 2, F_RES = 4, F_MULX = 16, F_ROWB = 32 };

#define TILE_BYTES  10240            // 128 rows x 80B
#define STAGE_BYTES (4 * TILE_BYTES) // Ahi, Alo, Bhi, Blo
#define GSMEM_TOTAL (2 * STAGE_BYTES)

template <int FLAGS>
__global__ void __launch_bounds__(256, 1) gemm_bf3(
    const __nv_bfloat16* __restrict__ Ahi, const __nv_bfloat16* __restrict__ Alo,
    const __nv_bfloat16* __restrict__ Bhi, const __nv_bfloat16* __restrict__ Blo,
    const float* __restrict__ bias, const float* __restrict__ rbias,
    const float* __restrict__ Xm, int ldx,
    const float* __restrict__ resid,
    float* __restrict__ C, int M, int N, int K) {

    extern __shared__ char dsm[];
    const uint32_t smem_base = s2u(dsm);

    const int tid  = threadIdx.x;
    const int wid  = tid >> 5;
    const int lane = tid & 31;
    const int wm   = wid >> 1;      // 0..3 -> rows wm*32
    const int wn   = wid & 1;       // 0..1 -> cols wn*64
    const int bm = blockIdx.y * 128, bn = blockIdx.x * 128;

    float acc[2][8][4];
    #pragma unroll
    for (int i = 0; i < 2; i++)
        #pragma unroll
        for (int j = 0; j < 8; j++)
            #pragma unroll
            for (int e = 0; e < 4; e++) acc[i][j][e] = 0.f;

    const __nv_bfloat16* bases[4] = {
        Ahi + (size_t)bm * K, Alo + (size_t)bm * K,
        Bhi + (size_t)bn * K, Blo + (size_t)bn * K };

    // ldmatrix lane geometry
    const int mi  = lane >> 3;       // matrix id 0..3
    const int lr8 = lane & 7;
    const int a_off = ((mi & 1) * 8 + lr8) * 80 + (mi >> 1) * 16;
    const int b_off = ((mi >> 1) * 8 + lr8) * 80 + (mi & 1) * 16;

    const int nK = K >> 5;

    // loader: 8 x 16B chunks per thread per stage
    #define LOAD_STAGE(s, kt) do {                                             \
        uint32_t sb_ = smem_base + (s) * STAGE_BYTES;                          \
        int kc_ = (kt) << 5;                                                   \
        _Pragma("unroll")                                                      \
        for (int t = 0; t < 8; t++) {                                          \
            int tile = t >> 1;                                                 \
            int w = ((t & 1) << 8) + tid;                                      \
            int row = w >> 2, ch = w & 3;                                      \
            const char* src = (const char*)(bases[tile] + (size_t)row * K + kc_ + ch * 8); \
            uint32_t dst = sb_ + tile * TILE_BYTES + row * 80 + ch * 16;       \
            CP_ASYNC16(dst, src);                                              \
        }                                                                      \
        CP_COMMIT();                                                           \
    } while (0)

    LOAD_STAGE(0, 0);

    for (int kt = 0; kt < nK; kt++) {
        int s = kt & 1;
        if (kt + 1 < nK) {
            LOAD_STAGE(s ^ 1, kt + 1);
            CP_WAIT1();
        } else {
            CP_WAIT0();
        }
        __syncthreads();

        uint32_t TAh = smem_base + s * STAGE_BYTES;
        uint32_t TAl = TAh + TILE_BYTES;
        uint32_t TBh = TAh + 2 * TILE_BYTES;
        uint32_t TBl = TAh + 3 * TILE_BYTES;

        #pragma unroll
        for (int ks = 0; ks < 2; ks++) {
            uint32_t ah[2][4], al_[2][4];
            #pragma unroll
            for (int mt = 0; mt < 2; mt++) {
                int rb = (wm * 32 + mt * 16) * 80 + ks * 32;
                LDSM4(ah[mt],  TAh + rb + a_off);
                LDSM4(al_[mt], TAl + rb + a_off);
            }
            uint32_t bh[4][4], bl[4][4];
            #pragma unroll
            for (int up = 0; up < 4; up++) {
                int rb = (wn * 64 + up * 16) * 80 + ks * 32;
                LDSM4(bh[up], TBh + rb + b_off);
                LDSM4(bl[up], TBl + rb + b_off);
            }
            #pragma unroll
            for (int mt = 0; mt < 2; mt++) {
                #pragma unroll
                for (int up = 0; up < 4; up++) {
                    float* c0 = acc[mt][2 * up];
                    float* c1 = acc[mt][2 * up + 1];
                    mma_bf16(c0, ah[mt],  &bh[up][0]);
                    mma_bf16(c0, ah[mt],  &bl[up][0]);
                    mma_bf16(c0, al_[mt], &bh[up][0]);
                    mma_bf16(c1, ah[mt],  &bh[up][2]);
                    mma_bf16(c1, ah[mt],  &bl[up][2]);
                    mma_bf16(c1, al_[mt], &bh[up][2]);
                }
            }
        }
        __syncthreads();
    }

    // ---- epilogue (fragment layout m16n8: row=lane>>2 (+8), col=(lane&3)*2 (+1)) ----
    const int r0 = bm + wm * 32 + (lane >> 2);
    const int cb = bn + wn * 64 + (lane & 3) * 2;
    #pragma unroll
    for (int mt = 0; mt < 2; mt++) {
        #pragma unroll
        for (int nt = 0; nt < 8; nt++) {
            float* a4 = acc[mt][nt];
            int gm = r0 + mt * 16;
            int gn = cb + nt * 8;
            #pragma unroll
            for (int e = 0; e < 4; e++) {
                int rr = gm + (e >> 1) * 8;
                int cc = gn + (e & 1);
                float v = a4[e];
                if (FLAGS & F_BIAS) v += bias[cc];
                if (FLAGS & F_ROWB) v += rbias[rr];
                if (FLAGS & F_GELU) v = gelu_f(v);
                if (FLAGS & F_MULX) v *= Xm[(size_t)rr * ldx + cc];
                if (FLAGS & F_RES)  v += resid[(size_t)rr * N + cc];
                C[(size_t)rr * N + cc] = v;
            }
        }
    }
}

// ---------------------------------------------------------------------------
// Exact fp32 SIMT GEMM for the head (N=32): C = A@B + bias
// ---------------------------------------------------------------------------
__global__ void __launch_bounds__(256) gemm_head(
    const float* __restrict__ A, const float* __restrict__ B,
    const float* __restrict__ bias, float* __restrict__ C,
    int M, int N, int K) {
    __shared__ float As[16][128];
    __shared__ float Bs[16][32];
    const int tid = threadIdx.x;
    const int bm = blockIdx.y * 128;
    const int r = tid >> 1;
    const int cp = (tid & 1) * 16;
    float acc[16];
    #pragma unroll
    for (int j = 0; j < 16; j++) acc[j] = 0.f;

    const int a_row = tid >> 2, a_col = (tid & 3) << 2;
    const int b_row = tid >> 3, b_col = (tid & 7) << 2;

    for (int kt = 0; kt < K; kt += 16) {
        #pragma unroll
        for (int rr = 0; rr < 2; rr++) {
            int lm = a_row + rr * 64;
            float4 v = *(const float4*)(A + (size_t)(bm + lm) * K + kt + a_col);
            As[a_col + 0][lm] = v.x; As[a_col + 1][lm] = v.y;
            As[a_col + 2][lm] = v.z; As[a_col + 3][lm] = v.w;
        }
        if (b_row < 16) {
            float4 v = *(const float4*)(B + (size_t)(kt + b_row) * N + b_col);
            *(float4*)&Bs[b_row][b_col] = v;
        }
        __syncthreads();
        #pragma unroll
        for (int kk = 0; kk < 16; kk++) {
            float a = As[kk][r];
            #pragma unroll
            for (int j = 0; j < 16; j++) acc[j] += a * Bs[kk][cp + j];
        }
        __syncthreads();
    }
    #pragma unroll
    for (int j = 0; j < 16; j++)
        C[(size_t)(bm + r) * N + cp + j] = acc[j] + bias[cp + j];
}

// ---------------------------------------------------------------------------
// Local windowed attention (flash-style, one thread per query row)
// ---------------------------------------------------------------------------
__global__ void __launch_bounds__(128) attn_kernel(const float* __restrict__ qkv,
                                                   float* __restrict__ out) {
    const int h  = blockIdx.z;
    const int w  = blockIdx.y;
    const int rc = blockIdx.x;
    const int i  = rc * 128 + threadIdx.x;
    const int t  = w * WSZ + i;

    float q[64];
    {
        const float4* qp = (const float4*)(qkv + (size_t)t * (3 * INNER) + h * DHEAD);
        #pragma unroll
        for (int d = 0; d < 16; d++) {
            float4 v = qp[d];
            q[4 * d + 0] = v.x * 0.125f;
            q[4 * d + 1] = v.y * 0.125f;
            q[4 * d + 2] = v.z * 0.125f;
            q[4 * d + 3] = v.w * 0.125f;
        }
    }
    float o[64];
    #pragma unroll
    for (int d = 0; d < 64; d++) o[d] = 0.f;
    float m = -1e30f, l = 0.f;

    __shared__ float Ks[32][64];
    __shared__ float Vs[32][64];

    const int lr = threadIdx.x >> 2;
    const int lc = (threadIdx.x & 3) * 16;
    const int nchunk = min(32, rc * 4 + 20);

    for (int c = 0; c < nchunk; c++) {
        int j0 = c * 32;
        int tok = (w - 1) * WSZ + j0 + lr;
        const float* kp = qkv + (size_t)tok * (3 * INNER) + INNER + h * DHEAD + lc;
        const float* vp = kp + INNER;
        #pragma unroll
        for (int e = 0; e < 4; e++) {
            float4 kv = make_float4(0.f, 0.f, 0.f, 0.f);
            float4 vv = make_float4(0.f, 0.f, 0.f, 0.f);
            if (tok >= 0) {
                kv = *(const float4*)(kp + 4 * e);
                vv = *(const float4*)(vp + 4 * e);
            }
            *(float4*)&Ks[lr][lc + 4 * e] = kv;
            *(float4*)&Vs[lr][lc + 4 * e] = vv;
        }
        __syncthreads();

        float s[32];
        float mnew = m;
        #pragma unroll
        for (int jj = 0; jj < 32; jj++) {
            float sv = -1e30f;
            if (j0 + jj <= i + WSZ) {
                sv = 0.f;
                #pragma unroll
                for (int d = 0; d < 64; d++) sv += q[d] * Ks[jj][d];
            }
            s[jj] = sv;
            mnew = fmaxf(mnew, sv);
        }
        float corr = __expf(m - mnew);
        l *= corr;
        #pragma unroll
        for (int d = 0; d < 64; d++) o[d] *= corr;
        #pragma unroll
        for (int jj = 0; jj < 32; jj++) {
            float p = __expf(s[jj] - mnew);
            l += p;
            #pragma unroll
            for (int d = 0; d < 64; d++) o[d] += p * Vs[jj][d];
        }
        m = mnew;
        __syncthreads();
    }

    float inv = 1.f / l;
    float4* op = (float4*)(out + (size_t)t * INNER + h * DHEAD);
    #pragma unroll
    for (int d = 0; d < 16; d++) {
        float4 v;
        v.x = o[4 * d + 0] * inv;
        v.y = o[4 * d + 1] * inv;
        v.z = o[4 * d + 2] * inv;
        v.w = o[4 * d + 3] * inv;
        op[d] = v;
    }
}

// ---------------------------------------------------------------------------
// Host-side dispatch
// ---------------------------------------------------------------------------
static __nv_bfloat16 *AHI, *ALO, *BHI, *BLO;

static void gemm(int flags, const float* A, const float* B, const float* bias,
                 const float* rbias, const float* Xm, int ldx, const float* resid,
                 float* C, int M, int N, int K, int tril) {
    splitA_k<<<(M * K / 4 + 255) / 256, 256>>>(A, AHI, ALO, M * K, K, tril);
    tspB_k<<<dim3(N / 32, K / 32), 256>>>(B, BHI, BLO, K, N);
    dim3 grid(N / 128, M / 128);
    switch (flags) {
        case 0:
            gemm_bf3<0><<<grid, 256, GSMEM_TOTAL>>>(AHI, ALO, BHI, BLO, bias, rbias, Xm, ldx, resid, C, M, N, K); break;
        case F_BIAS:
            gemm_bf3<F_BIAS><<<grid, 256, GSMEM_TOTAL>>>(AHI, ALO, BHI, BLO, bias, rbias, Xm, ldx, resid, C, M, N, K); break;
        case F_BIAS | F_RES:
            gemm_bf3<F_BIAS | F_RES><<<grid, 256, GSMEM_TOTAL>>>(AHI, ALO, BHI, BLO, bias, rbias, Xm, ldx, resid, C, M, N, K); break;
        case F_BIAS | F_GELU:
            gemm_bf3<F_BIAS | F_GELU><<<grid, 256, GSMEM_TOTAL>>>(AHI, ALO, BHI, BLO, bias, rbias, Xm, ldx, resid, C, M, N, K); break;
        case F_ROWB | F_MULX:
            gemm_bf3<F_ROWB | F_MULX><<<grid, 256, GSMEM_TOTAL>>>(AHI, ALO, BHI, BLO, bias, rbias, Xm, ldx, resid, C, M, N, K); break;
    }
}

extern "C" void kernel_launch(void* const* d_in, const int* in_sizes, int n_in,
                              void* d_out, int out_size) {
    (void)in_sizes; (void)n_in;
    const int*   tokens   = (const int*)  d_in[0];
    const float* embed    = (const float*)d_in[1];
    const float* attn_ln  = (const float*)d_in[2];
    const float* attn_qkv = (const float*)d_in[3];
    const float* attn_ow  = (const float*)d_in[4];
    const float* attn_ob  = (const float*)d_in[5];
    const float* ff_ln    = (const float*)d_in[6];
    const float* ff_w1    = (const float*)d_in[7];
    const float* ff_b1    = (const float*)d_in[8];
    const float* ff_w2    = (const float*)d_in[9];
    const float* ff_b2    = (const float*)d_in[10];
    const float* gl_ln    = (const float*)d_in[11];
    const float* g_win    = (const float*)d_in[12];
    const float* g_bin    = (const float*)d_in[13];
    const float* g_sln    = (const float*)d_in[14];
    const float* g_sw     = (const float*)d_in[15];
    const float* g_sb     = (const float*)d_in[16];
    const float* g_sow    = (const float*)d_in[17];
    const float* g_sob    = (const float*)d_in[18];
    const float* g_pow    = (const float*)d_in[19];
    const float* g_pob    = (const float*)d_in[20];
    const float* fin_ln   = (const float*)d_in[21];
    const float* head_w   = (const float*)d_in[22];
    const float* head_b   = (const float*)d_in[23];
    float* out = (float*)d_out;
    (void)out_size;

    float *X, *XN, *QKV, *ATT, *H, *GT, *TP;
    cudaGetSymbolAddress((void**)&X,   g_x);
    cudaGetSymbolAddress((void**)&XN,  g_xn);
    cudaGetSymbolAddress((void**)&QKV, g_qkv);
    cudaGetSymbolAddress((void**)&ATT, g_att);
    cudaGetSymbolAddress((void**)&H,   g_h);
    cudaGetSymbolAddress((void**)&GT,  g_gt);
    cudaGetSymbolAddress((void**)&TP,  g_tp);
    cudaGetSymbolAddress((void**)&AHI, g_ahi);
    cudaGetSymbolAddress((void**)&ALO, g_alo);
    cudaGetSymbolAddress((void**)&BHI, g_bhi);
    cudaGetSymbolAddress((void**)&BLO, g_blo);

    cudaFuncSetAttribute(gemm_bf3<0>, cudaFuncAttributeMaxDynamicSharedMemorySize, GSMEM_TOTAL);
    cudaFuncSetAttribute(gemm_bf3<F_BIAS>, cudaFuncAttributeMaxDynamicSharedMemorySize, GSMEM_TOTAL);
    cudaFuncSetAttribute(gemm_bf3<F_BIAS | F_RES>, cudaFuncAttributeMaxDynamicSharedMemorySize, GSMEM_TOTAL);
    cudaFuncSetAttribute(gemm_bf3<F_BIAS | F_GELU>, cudaFuncAttributeMaxDynamicSharedMemorySize, GSMEM_TOTAL);
    cudaFuncSetAttribute(gemm_bf3<F_ROWB | F_MULX>, cudaFuncAttributeMaxDynamicSharedMemorySize, GSMEM_TOTAL);

    embed_kernel<<<N_TOK, 256>>>(tokens, embed, X);

    for (int l = 0; l < DEPTH; l++) {
        const float* al = attn_ln  + (size_t)l * DIM;
        const float* aq = attn_qkv + (size_t)l * DIM * 3 * INNER;
        const float* aw = attn_ow  + (size_t)l * INNER * DIM;
        const float* ab = attn_ob  + (size_t)l * DIM;
        const float* fl = ff_ln    + (size_t)l * DIM;
        const float* f1 = ff_w1    + (size_t)l * DIM * DFF;
        const float* b1 = ff_b1    + (size_t)l * DFF;
        const float* f2 = ff_w2    + (size_t)l * DFF * DIM;
        const float* b2 = ff_b2    + (size_t)l * DIM;

        ln_kernel<<<N_TOK, 256>>>(X, DIM, al, XN, DIM, DIM);
        gemm(0, XN, aq, nullptr, nullptr, nullptr, 0, nullptr, QKV, N_TOK, 3 * INNER, DIM, 0);
        attn_kernel<<<dim3(4, 4, NHEAD), 128>>>(QKV, ATT);
        gemm(F_BIAS | F_RES, ATT, aw, ab, nullptr, nullptr, 0, X, X, N_TOK, DIM, INNER, 0);

        ln_kernel<<<N_TOK, 256>>>(X, DIM, fl, XN, DIM, DIM);
        gemm(F_BIAS | F_GELU, XN, f1, b1, nullptr, nullptr, 0, nullptr, H, N_TOK, DFF, DIM, 0);
        gemm(F_BIAS | F_RES, H, f2, b2, nullptr, nullptr, 0, X, X, N_TOK, DIM, DFF, 0);
    }

    for (int g = 0; g < GDEPTH; g++) {
        const float* gl  = gl_ln + (size_t)g * DIM;
        const float* wi  = g_win + (size_t)g * DIM * DFF;
        const float* bi  = g_bin + (size_t)g * DFF;
        const float* sl  = g_sln + (size_t)g * HALF;
        const float* sw  = g_sw  + (size_t)g * N_TOK * N_TOK;
        const float* sb  = g_sb  + (size_t)g * N_TOK;
        const float* so  = g_sow + (size_t)g * HALF * HALF;
        const float* sob = g_sob + (size_t)g * HALF;
        const float* po  = g_pow + (size_t)g * HALF * DIM;
        const float* pob = g_pob + (size_t)g * DIM;

        ln_kernel<<<N_TOK, 256>>>(X, DIM, gl, XN, DIM, DIM);
        gemm(F_BIAS | F_GELU, XN, wi, bi, nullptr, nullptr, 0, nullptr, H, N_TOK, DFF, DIM, 0);
        ln_kernel<<<N_TOK, 256>>>(H + HALF, DFF, sl, GT, HALF, HALF);
        // TP = xg * (tril(sw) @ gate + sb)
        gemm(F_ROWB | F_MULX, sw, GT, nullptr, sb, H, DFF, nullptr, TP,
             N_TOK, HALF, N_TOK, 1);
        gemm(F_BIAS, TP, so, sob, nullptr, nullptr, 0, nullptr, GT, N_TOK, HALF, HALF, 0);
        gemm(F_BIAS | F_RES, GT, po, pob, nullptr, nullptr, 0, X, X, N_TOK, DIM, HALF, 0);
    }

    ln_kernel<<<N_TOK, 256>>>(X, DIM, fin_ln, XN, DIM, DIM);
    gemm_head<<<dim3(1, N_TOK / 128), 256>>>(XN, head_w, head_b, out, N_TOK, VOCAB, DIM);
}